// round 14
// baseline (speedup 1.0000x reference)
#include <cuda_runtime.h>
#include <cuda_fp16.h>
#include <math.h>

// FilterInterpolationModule: adaptive 4x4 filter + bilinear warp.
// 16 taps x 4 bilinear corners collapse to an effective per-pixel 5x5 kernel.
//
// R14 = R10 exactly (fp16 gather payload = L1 byte floor; plain bounds;
// default-cache loads) + capture-fork overlap ONLY (single variable retest;
// R11 confounded the fork with __ldcs poisoning):
//   repack(0) -> fork -> side stream repack(1..3) || main(0) -> join ->
//   main(1..3).

namespace {
constexpr int H  = 544;
constexpr int W  = 960;
constexpr int C  = 3;
constexpr int FS = 4;
constexpr int HW = H * W;   // 522240 = 2040 * 256 = 255 * 2048
constexpr int BMAX = 4;
}

// Static device scratch (no runtime alloc): 8.4 MB + 4.2 MB.
__device__ __half2 g_img01[BMAX * HW];
__device__ __half  g_img2 [BMAX * HW];

__global__ __launch_bounds__(256) void repack_kernel(
    const float* __restrict__ input1,   // [B, C, H, W]
    int b0)
{
    const int q   = blockIdx.x * blockDim.x + threadIdx.x;   // 8-pixel group
    const int b   = blockIdx.y + b0;
    const int pix = q * 8;

    const float* p = input1 + (size_t)(b * C) * HW + pix;

#pragma unroll
    for (int h = 0; h < 2; h++) {
        const int o = h * 4;
        const float4 v0 = *(const float4*)(p + 0 * HW + o);
        const float4 v1 = *(const float4*)(p + 1 * HW + o);
        const float4 v2 = *(const float4*)(p + 2 * HW + o);

        __half2 h01[4];
        h01[0] = __floats2half2_rn(v0.x, v1.x);
        h01[1] = __floats2half2_rn(v0.y, v1.y);
        h01[2] = __floats2half2_rn(v0.z, v1.z);
        h01[3] = __floats2half2_rn(v0.w, v1.w);
        *(uint4*)(g_img01 + b * HW + pix + o) = *(const uint4*)h01;

        __half h2[4];
        h2[0] = __float2half_rn(v2.x);
        h2[1] = __float2half_rn(v2.y);
        h2[2] = __float2half_rn(v2.z);
        h2[3] = __float2half_rn(v2.w);
        *(uint2*)(g_img2 + b * HW + pix + o) = *(const uint2*)h2;
    }
}

__global__ __launch_bounds__(256) void filter_interp_kernel(
    const float* __restrict__ input2,   // [B, 2, H, W]  (fx, fy)
    const float* __restrict__ input3,   // [B, 16, H, W]
    float* __restrict__ out,            // [B, C, H, W]
    int b0)
{
    const int pix = blockIdx.x * blockDim.x + threadIdx.x;  // exact grid
    const int b   = blockIdx.y + b0;

    const int y = pix / W;
    const int x = pix - y * W;

    const float fx = __ldg(input2 + (b * 2 + 0) * HW + pix);
    const float fy = __ldg(input2 + (b * 2 + 1) * HW + pix);

    const float x2 = (float)x + fx;
    const float y2 = (float)y + fy;

    const bool mask =
        (x2 >= 0.0f) && (y2 >= 0.0f) &&
        (x2 <= (float)(W - 1)) && (y2 <= (float)(H - 1)) &&
        (fabsf(fx) < (float)W * 0.5f) && (fabsf(fy) < (float)H * 0.5f);

    float* outp = out + (size_t)(b * C) * HW + pix;

    if (!mask) {
#pragma unroll
        for (int c = 0; c < C; c++) outp[c * HW] = 0.0f;
        return;
    }

    const float x2c = fminf(fmaxf(x2, 0.0f), (float)(W - 1));
    const float y2c = fminf(fmaxf(y2, 0.0f), (float)(H - 1));
    const int ix = (int)floorf(x2c);
    const int iy = (int)floorf(y2c);
    const float alpha = x2c - (float)ix;
    const float beta  = y2c - (float)iy;
    const int ixL = ix - 1;   // ix + 1 - fs/2
    const int iyT = iy - 1;

    const float wa = (1.0f - alpha) * (1.0f - beta);
    const float wb = alpha * (1.0f - beta);
    const float wc = (1.0f - alpha) * beta;
    const float wd = alpha * beta;

    // Effective 5x5 weights from 4x4 filter taps x bilinear corners.
    float eff[5][5];
#pragma unroll
    for (int j = 0; j < 5; j++)
#pragma unroll
        for (int i = 0; i < 5; i++) eff[j][i] = 0.0f;

    const float* w3p = input3 + (size_t)(b * FS * FS) * HW + pix;
#pragma unroll
    for (int j = 0; j < FS; j++) {
#pragma unroll
        for (int i = 0; i < FS; i++) {
            const float w = __ldg(w3p + (j * FS + i) * HW);
            eff[j][i]         += wa * w;
            eff[j][i + 1]     += wb * w;
            eff[j + 1][i]     += wc * w;
            eff[j + 1][i + 1] += wd * w;
        }
    }

    // Clamped patch indices (matches reference's per-tap clipping exactly).
    int rowOff[5];
    int colIdx[5];
#pragma unroll
    for (int k = 0; k < 5; k++) {
        int r = iyT + k;
        r = min(max(r, 0), H - 1);
        rowOff[k] = r * W;
        int cc = ixL + k;
        cc = min(max(cc, 0), W - 1);
        colIdx[k] = cc;
    }

    const __half2* imgA = g_img01 + b * HW;
    const __half*  imgB = g_img2  + b * HW;

    float acc0 = 0.0f, acc1 = 0.0f, acc2 = 0.0f;
#pragma unroll
    for (int j = 0; j < 5; j++) {
        const int ro = rowOff[j];
#pragma unroll
        for (int i = 0; i < 5; i++) {
            const int idx = ro + colIdx[i];
            const __half2 h01 = __ldg(imgA + idx);
            const __half  h2  = __ldg(imgB + idx);
            const float2  f01 = __half22float2(h01);
            const float e = eff[j][i];
            acc0 = fmaf(e, f01.x, acc0);
            acc1 = fmaf(e, f01.y, acc1);
            acc2 = fmaf(e, __half2float(h2), acc2);
        }
    }

    outp[0 * HW] = acc0;
    outp[1 * HW] = acc1;
    outp[2 * HW] = acc2;
}

extern "C" void kernel_launch(void* const* d_in, const int* in_sizes, int n_in,
                              void* d_out, int out_size) {
    const float* input1 = (const float*)d_in[0];
    const float* input2 = (const float*)d_in[1];
    const float* input3 = (const float*)d_in[2];
    float* out = (float*)d_out;

    const int B = in_sizes[1] / (2 * HW);

    // Host-side resources created once (no device memory involved).
    static cudaStream_t s1 = nullptr;
    static cudaEvent_t evFork = nullptr, evSide = nullptr;
    if (s1 == nullptr) {
        cudaStreamCreateWithFlags(&s1, cudaStreamNonBlocking);
        cudaEventCreateWithFlags(&evFork, cudaEventDisableTiming);
        cudaEventCreateWithFlags(&evSide, cudaEventDisableTiming);
    }

    dim3 block(256);
    const int gR = HW / (8 * 256);   // 255, exact
    const int gM = HW / 256;         // 2040, exact

    // Batch 0 repack on the main (capture) stream.
    repack_kernel<<<dim3(gR, 1), block>>>(input1, 0);

    if (B > 1) {
        // Fork: batches 1..B-1 repack on the side stream, intended to run
        // concurrently with main(0).
        cudaEventRecord(evFork, 0);
        cudaStreamWaitEvent(s1, evFork, 0);
        repack_kernel<<<dim3(gR, B - 1), block, 0, s1>>>(input1, 1);
        cudaEventRecord(evSide, s1);
    }

    // main(0) overlaps with side-stream repacks (if the graph keeps the fork).
    filter_interp_kernel<<<dim3(gM, 1), block>>>(input2, input3, out, 0);

    if (B > 1) {
        cudaStreamWaitEvent(0, evSide, 0);
        filter_interp_kernel<<<dim3(gM, B - 1), block>>>(input2, input3, out, 1);
    }
}

// round 15
// speedup vs baseline: 1.4802x; 1.4802x over previous
#include <cuda_runtime.h>
#include <cuda_fp16.h>
#include <math.h>

// FilterInterpolationModule: adaptive 4x4 filter + bilinear warp.
// 16 taps x 4 bilinear corners collapse to an effective per-pixel 5x5 kernel.
//
// R15 = R10 (fp16 gather payload = L1 byte floor; single stream; plain
// bounds) + 2D block tiling: each 256-thread block covers a 64x4 pixel tile
// (instead of 256x1), shrinking the per-block gather footprint ~18KB -> ~8KB
// for a higher L1 hit rate on the 5x tap-overlap reuse. Warp-level
// coalescing of flow/weight/output accesses is preserved (warp = 32
// consecutive x at a single y).

namespace {
constexpr int H  = 544;
constexpr int W  = 960;
constexpr int C  = 3;
constexpr int FS = 4;
constexpr int HW = H * W;   // 522240
constexpr int BMAX = 4;

constexpr int TX = 64;      // tile width
constexpr int TY = 4;       // tile height
constexpr int TILES_X = W / TX;   // 15
constexpr int TILES_Y = H / TY;   // 136
}

// Static device scratch (no runtime alloc): 8.4 MB + 4.2 MB.
__device__ __half2 g_img01[BMAX * HW];
__device__ __half  g_img2 [BMAX * HW];

__global__ __launch_bounds__(256) void repack_kernel(
    const float* __restrict__ input1)   // [B, C, H, W]
{
    const int q   = blockIdx.x * blockDim.x + threadIdx.x;   // 8-pixel group
    const int b   = blockIdx.y;
    const int pix = q * 8;

    const float* p = input1 + (size_t)(b * C) * HW + pix;

#pragma unroll
    for (int h = 0; h < 2; h++) {
        const int o = h * 4;
        const float4 v0 = *(const float4*)(p + 0 * HW + o);
        const float4 v1 = *(const float4*)(p + 1 * HW + o);
        const float4 v2 = *(const float4*)(p + 2 * HW + o);

        __half2 h01[4];
        h01[0] = __floats2half2_rn(v0.x, v1.x);
        h01[1] = __floats2half2_rn(v0.y, v1.y);
        h01[2] = __floats2half2_rn(v0.z, v1.z);
        h01[3] = __floats2half2_rn(v0.w, v1.w);
        *(uint4*)(g_img01 + b * HW + pix + o) = *(const uint4*)h01;

        __half h2[4];
        h2[0] = __float2half_rn(v2.x);
        h2[1] = __float2half_rn(v2.y);
        h2[2] = __float2half_rn(v2.z);
        h2[3] = __float2half_rn(v2.w);
        *(uint2*)(g_img2 + b * HW + pix + o) = *(const uint2*)h2;
    }
}

__global__ __launch_bounds__(256) void filter_interp_kernel(
    const float* __restrict__ input2,   // [B, 2, H, W]  (fx, fy)
    const float* __restrict__ input3,   // [B, 16, H, W]
    float* __restrict__ out)            // [B, C, H, W]
{
    const int tid   = threadIdx.x;
    const int tileX = blockIdx.x % TILES_X;
    const int tileY = blockIdx.x / TILES_X;
    const int b     = blockIdx.y;

    const int x = tileX * TX + (tid & (TX - 1));
    const int y = tileY * TY + (tid >> 6);
    const int pix = y * W + x;

    const float fx = __ldg(input2 + (b * 2 + 0) * HW + pix);
    const float fy = __ldg(input2 + (b * 2 + 1) * HW + pix);

    const float x2 = (float)x + fx;
    const float y2 = (float)y + fy;

    const bool mask =
        (x2 >= 0.0f) && (y2 >= 0.0f) &&
        (x2 <= (float)(W - 1)) && (y2 <= (float)(H - 1)) &&
        (fabsf(fx) < (float)W * 0.5f) && (fabsf(fy) < (float)H * 0.5f);

    float* outp = out + (size_t)(b * C) * HW + pix;

    if (!mask) {
#pragma unroll
        for (int c = 0; c < C; c++) outp[c * HW] = 0.0f;
        return;
    }

    const float x2c = fminf(fmaxf(x2, 0.0f), (float)(W - 1));
    const float y2c = fminf(fmaxf(y2, 0.0f), (float)(H - 1));
    const int ix = (int)floorf(x2c);
    const int iy = (int)floorf(y2c);
    const float alpha = x2c - (float)ix;
    const float beta  = y2c - (float)iy;
    const int ixL = ix - 1;   // ix + 1 - fs/2
    const int iyT = iy - 1;

    const float wa = (1.0f - alpha) * (1.0f - beta);
    const float wb = alpha * (1.0f - beta);
    const float wc = (1.0f - alpha) * beta;
    const float wd = alpha * beta;

    // Effective 5x5 weights from 4x4 filter taps x bilinear corners.
    float eff[5][5];
#pragma unroll
    for (int j = 0; j < 5; j++)
#pragma unroll
        for (int i = 0; i < 5; i++) eff[j][i] = 0.0f;

    const float* w3p = input3 + (size_t)(b * FS * FS) * HW + pix;
#pragma unroll
    for (int j = 0; j < FS; j++) {
#pragma unroll
        for (int i = 0; i < FS; i++) {
            const float w = __ldg(w3p + (j * FS + i) * HW);
            eff[j][i]         += wa * w;
            eff[j][i + 1]     += wb * w;
            eff[j + 1][i]     += wc * w;
            eff[j + 1][i + 1] += wd * w;
        }
    }

    // Clamped patch indices (matches reference's per-tap clipping exactly).
    int rowOff[5];
    int colIdx[5];
#pragma unroll
    for (int k = 0; k < 5; k++) {
        int r = iyT + k;
        r = min(max(r, 0), H - 1);
        rowOff[k] = r * W;
        int cc = ixL + k;
        cc = min(max(cc, 0), W - 1);
        colIdx[k] = cc;
    }

    const __half2* imgA = g_img01 + b * HW;
    const __half*  imgB = g_img2  + b * HW;

    float acc0 = 0.0f, acc1 = 0.0f, acc2 = 0.0f;
#pragma unroll
    for (int j = 0; j < 5; j++) {
        const int ro = rowOff[j];
#pragma unroll
        for (int i = 0; i < 5; i++) {
            const int idx = ro + colIdx[i];
            const __half2 h01 = __ldg(imgA + idx);
            const __half  h2  = __ldg(imgB + idx);
            const float2  f01 = __half22float2(h01);
            const float e = eff[j][i];
            acc0 = fmaf(e, f01.x, acc0);
            acc1 = fmaf(e, f01.y, acc1);
            acc2 = fmaf(e, __half2float(h2), acc2);
        }
    }

    outp[0 * HW] = acc0;
    outp[1 * HW] = acc1;
    outp[2 * HW] = acc2;
}

extern "C" void kernel_launch(void* const* d_in, const int* in_sizes, int n_in,
                              void* d_out, int out_size) {
    const float* input1 = (const float*)d_in[0];
    const float* input2 = (const float*)d_in[1];
    const float* input3 = (const float*)d_in[2];
    float* out = (float*)d_out;

    const int B = in_sizes[1] / (2 * HW);

    dim3 block(256);
    dim3 gridR(HW / (8 * 256), B);              // exact: 255
    repack_kernel<<<gridR, block>>>(input1);

    dim3 gridM(TILES_X * TILES_Y, B);           // exact: 2040
    filter_interp_kernel<<<gridM, block>>>(input2, input3, out);
}

// round 16
// speedup vs baseline: 1.5292x; 1.0331x over previous
#include <cuda_runtime.h>
#include <cuda_fp16.h>
#include <math.h>

// FilterInterpolationModule: adaptive 4x4 filter + bilinear warp.
// 16 taps x 4 bilinear corners collapse to an effective per-pixel 5x5 kernel.
//
// R16 = R15 (fp16 gather payload; 2D block tiling) with a squarer 32x8 tile
// (warp = one 32-px row strip, coalescing unchanged; block gather footprint
// 6.6KB -> 5.4KB, vertical tap overlap shared across 8 in-block rows) and a
// 4 px/thread repack (more blocks -> evener waves).

namespace {
constexpr int H  = 544;
constexpr int W  = 960;
constexpr int C  = 3;
constexpr int FS = 4;
constexpr int HW = H * W;   // 522240
constexpr int BMAX = 4;

constexpr int TX = 32;      // tile width
constexpr int TY = 8;       // tile height
constexpr int TILES_X = W / TX;   // 30
constexpr int TILES_Y = H / TY;   // 68
}

// Static device scratch (no runtime alloc): 8.4 MB + 4.2 MB.
__device__ __half2 g_img01[BMAX * HW];
__device__ __half  g_img2 [BMAX * HW];

__global__ __launch_bounds__(256) void repack_kernel(
    const float* __restrict__ input1)   // [B, C, H, W]
{
    const int q   = blockIdx.x * blockDim.x + threadIdx.x;   // 4-pixel group
    const int b   = blockIdx.y;
    const int pix = q * 4;

    const float* p = input1 + (size_t)(b * C) * HW + pix;
    const float4 v0 = *(const float4*)(p + 0 * HW);
    const float4 v1 = *(const float4*)(p + 1 * HW);
    const float4 v2 = *(const float4*)(p + 2 * HW);

    __half2 h01[4];
    h01[0] = __floats2half2_rn(v0.x, v1.x);
    h01[1] = __floats2half2_rn(v0.y, v1.y);
    h01[2] = __floats2half2_rn(v0.z, v1.z);
    h01[3] = __floats2half2_rn(v0.w, v1.w);
    *(uint4*)(g_img01 + b * HW + pix) = *(const uint4*)h01;

    __half h2[4];
    h2[0] = __float2half_rn(v2.x);
    h2[1] = __float2half_rn(v2.y);
    h2[2] = __float2half_rn(v2.z);
    h2[3] = __float2half_rn(v2.w);
    *(uint2*)(g_img2 + b * HW + pix) = *(const uint2*)h2;
}

__global__ __launch_bounds__(256) void filter_interp_kernel(
    const float* __restrict__ input2,   // [B, 2, H, W]  (fx, fy)
    const float* __restrict__ input3,   // [B, 16, H, W]
    float* __restrict__ out)            // [B, C, H, W]
{
    const int tid   = threadIdx.x;
    const int tileX = blockIdx.x % TILES_X;
    const int tileY = blockIdx.x / TILES_X;
    const int b     = blockIdx.y;

    const int x = tileX * TX + (tid & (TX - 1));
    const int y = tileY * TY + (tid >> 5);
    const int pix = y * W + x;

    const float fx = __ldg(input2 + (b * 2 + 0) * HW + pix);
    const float fy = __ldg(input2 + (b * 2 + 1) * HW + pix);

    const float x2 = (float)x + fx;
    const float y2 = (float)y + fy;

    const bool mask =
        (x2 >= 0.0f) && (y2 >= 0.0f) &&
        (x2 <= (float)(W - 1)) && (y2 <= (float)(H - 1)) &&
        (fabsf(fx) < (float)W * 0.5f) && (fabsf(fy) < (float)H * 0.5f);

    float* outp = out + (size_t)(b * C) * HW + pix;

    if (!mask) {
#pragma unroll
        for (int c = 0; c < C; c++) outp[c * HW] = 0.0f;
        return;
    }

    const float x2c = fminf(fmaxf(x2, 0.0f), (float)(W - 1));
    const float y2c = fminf(fmaxf(y2, 0.0f), (float)(H - 1));
    const int ix = (int)floorf(x2c);
    const int iy = (int)floorf(y2c);
    const float alpha = x2c - (float)ix;
    const float beta  = y2c - (float)iy;
    const int ixL = ix - 1;   // ix + 1 - fs/2
    const int iyT = iy - 1;

    const float wa = (1.0f - alpha) * (1.0f - beta);
    const float wb = alpha * (1.0f - beta);
    const float wc = (1.0f - alpha) * beta;
    const float wd = alpha * beta;

    // Effective 5x5 weights from 4x4 filter taps x bilinear corners.
    float eff[5][5];
#pragma unroll
    for (int j = 0; j < 5; j++)
#pragma unroll
        for (int i = 0; i < 5; i++) eff[j][i] = 0.0f;

    const float* w3p = input3 + (size_t)(b * FS * FS) * HW + pix;
#pragma unroll
    for (int j = 0; j < FS; j++) {
#pragma unroll
        for (int i = 0; i < FS; i++) {
            const float w = __ldg(w3p + (j * FS + i) * HW);
            eff[j][i]         += wa * w;
            eff[j][i + 1]     += wb * w;
            eff[j + 1][i]     += wc * w;
            eff[j + 1][i + 1] += wd * w;
        }
    }

    // Clamped patch indices (matches reference's per-tap clipping exactly).
    int rowOff[5];
    int colIdx[5];
#pragma unroll
    for (int k = 0; k < 5; k++) {
        int r = iyT + k;
        r = min(max(r, 0), H - 1);
        rowOff[k] = r * W;
        int cc = ixL + k;
        cc = min(max(cc, 0), W - 1);
        colIdx[k] = cc;
    }

    const __half2* imgA = g_img01 + b * HW;
    const __half*  imgB = g_img2  + b * HW;

    float acc0 = 0.0f, acc1 = 0.0f, acc2 = 0.0f;
#pragma unroll
    for (int j = 0; j < 5; j++) {
        const int ro = rowOff[j];
#pragma unroll
        for (int i = 0; i < 5; i++) {
            const int idx = ro + colIdx[i];
            const __half2 h01 = __ldg(imgA + idx);
            const __half  h2  = __ldg(imgB + idx);
            const float2  f01 = __half22float2(h01);
            const float e = eff[j][i];
            acc0 = fmaf(e, f01.x, acc0);
            acc1 = fmaf(e, f01.y, acc1);
            acc2 = fmaf(e, __half2float(h2), acc2);
        }
    }

    outp[0 * HW] = acc0;
    outp[1 * HW] = acc1;
    outp[2 * HW] = acc2;
}

extern "C" void kernel_launch(void* const* d_in, const int* in_sizes, int n_in,
                              void* d_out, int out_size) {
    const float* input1 = (const float*)d_in[0];
    const float* input2 = (const float*)d_in[1];
    const float* input3 = (const float*)d_in[2];
    float* out = (float*)d_out;

    const int B = in_sizes[1] / (2 * HW);

    dim3 block(256);
    dim3 gridR(HW / (4 * 256), B);              // exact: 510
    repack_kernel<<<gridR, block>>>(input1);

    dim3 gridM(TILES_X * TILES_Y, B);           // exact: 2040
    filter_interp_kernel<<<gridM, block>>>(input2, input3, out);
}